// round 13
// baseline (speedup 1.0000x reference)
#include <cuda_runtime.h>
#include <cuda_bf16.h>
#include <math.h>
#include <stdint.h>

#define TT 4096
#define KTOT (64*4096)   /* 262144 */
#define FD 512

// ---------------- scratch (static device globals) ----------------
__device__ __nv_bfloat16 g_Ah[(size_t)256 * KTOT];   // views: 0=x,1=distorted,2=noisy,3=combined
__device__ __nv_bfloat16 g_Al[(size_t)256 * KTOT];
__device__ __nv_bfloat16 g_Wh[(size_t)KTOT * FD];
__device__ __nv_bfloat16 g_Wl[(size_t)KTOT * FD];
__device__ float g_We[64 * FD];      // col-sums of W per c
__device__ float g_Wo[64 * FD];      // alternating col-sums
__device__ float g_X0[4096];         // per (b,c) row: sum of x
__device__ float g_X2048[4096];      // per (b,c) row: alternating sum
__device__ float g_feats[320 * FD];
__device__ float g_norms[320];
__device__ float g_cons;
__device__ float g_contr;

// ---------------- PTX helpers (baseline ISA only) ----------------
__device__ __forceinline__ uint32_t smem_to_u32(const void* p) {
    uint32_t a;
    asm("{ .reg .u64 t; cvta.to.shared.u64 t, %1; cvt.u32.u64 %0, t; }" : "=r"(a) : "l"(p));
    return a;
}
__device__ __forceinline__ void ldsm_x4(uint32_t* r, uint32_t addr) {
    asm volatile("ldmatrix.sync.aligned.m8n8.x4.shared.b16 {%0,%1,%2,%3}, [%4];"
        : "=r"(r[0]), "=r"(r[1]), "=r"(r[2]), "=r"(r[3]) : "r"(addr));
}
__device__ __forceinline__ void ldsm_x4_trans(uint32_t* r, uint32_t addr) {
    asm volatile("ldmatrix.sync.aligned.m8n8.x4.trans.shared.b16 {%0,%1,%2,%3}, [%4];"
        : "=r"(r[0]), "=r"(r[1]), "=r"(r[2]), "=r"(r[3]) : "r"(addr));
}
__device__ __forceinline__ void mma_bf16(float* c, const uint32_t* a, const uint32_t* b) {
    asm volatile("mma.sync.aligned.m16n8k16.row.col.f32.bf16.bf16.f32 "
        "{%0,%1,%2,%3}, {%4,%5,%6,%7}, {%8,%9}, {%0,%1,%2,%3};"
        : "+f"(c[0]), "+f"(c[1]), "+f"(c[2]), "+f"(c[3])
        : "r"(a[0]), "r"(a[1]), "r"(a[2]), "r"(a[3]), "r"(b[0]), "r"(b[1]));
}
__device__ __forceinline__ void cp_async16(uint32_t smem, const void* g) {
    asm volatile("cp.async.cg.shared.global [%0], [%1], 16;" :: "r"(smem), "l"(g));
}
#define CP_COMMIT() asm volatile("cp.async.commit_group;" ::: "memory")
#define CP_WAIT1()  asm volatile("cp.async.wait_group 1;" ::: "memory")
#define CP_WAIT0()  asm volatile("cp.async.wait_group 0;" ::: "memory")

// ---------------- block reductions ----------------
__device__ __forceinline__ float blockReduceSum(float v, float* red) {
    int lane = threadIdx.x & 31, w = threadIdx.x >> 5;
    int nw = blockDim.x >> 5;
    #pragma unroll
    for (int o = 16; o; o >>= 1) v += __shfl_down_sync(0xffffffffu, v, o);
    if (lane == 0) red[w] = v;
    __syncthreads();
    if (w == 0) {
        float r = (lane < nw) ? red[lane] : 0.0f;
        #pragma unroll
        for (int o = 8; o; o >>= 1) r += __shfl_down_sync(0xffffffffu, r, o);
        if (lane == 0) red[0] = r;
    }
    __syncthreads();
    float out = red[0];
    __syncthreads();
    return out;
}
__device__ __forceinline__ float blockReduceMax(float v, float* red) {
    int lane = threadIdx.x & 31, w = threadIdx.x >> 5;
    int nw = blockDim.x >> 5;
    #pragma unroll
    for (int o = 16; o; o >>= 1) v = fmaxf(v, __shfl_down_sync(0xffffffffu, v, o));
    if (lane == 0) red[w] = v;
    __syncthreads();
    if (w == 0) {
        float r = (lane < nw) ? red[lane] : -3.4e38f;
        #pragma unroll
        for (int o = 8; o; o >>= 1) r = fmaxf(r, __shfl_down_sync(0xffffffffu, r, o));
        if (lane == 0) red[0] = r;
    }
    __syncthreads();
    float out = red[0];
    __syncthreads();
    return out;
}

// ---------------- complex / masks / skew ----------------
__device__ __forceinline__ float2 f2add(float2 a, float2 b) { return make_float2(a.x + b.x, a.y + b.y); }
__device__ __forceinline__ float2 f2sub(float2 a, float2 b) { return make_float2(a.x - b.x, a.y - b.y); }
__device__ __forceinline__ float2 cmul(float2 a, float2 b) {
    return make_float2(a.x*b.x - a.y*b.y, a.x*b.y + a.y*b.x);
}
__device__ __forceinline__ float2 cmulc(float2 a, float2 b) {   // conj(a)*b
    return make_float2(a.x*b.x + a.y*b.y, a.x*b.y - a.y*b.x);
}
__device__ __forceinline__ float fmfold(int k, int fs) {
    float f1 = (k >= fs && k < fs + 409) ? 0.1f : 1.0f;
    int k2 = (4096 - k) & 4095;
    float f2 = (k2 >= fs && k2 < fs + 409) ? 0.1f : 1.0f;
    return 0.5f * (f1 + f2);
}
__device__ __forceinline__ float gmask(int k) {
    return (k == 0) ? 1.0f : ((k <= 1024) ? 0.5f : ((k < 3072) ? 1.0f : 0.5f));
}
__device__ __forceinline__ int skw3(int g) { return g + (g >> 3); }
#define PLANE3 4608

// ---------------- radix-8 butterfly ----------------
template<int FWD>
__device__ __forceinline__ void dft8(const float2* e, float2* y) {
    float2 a02s = f2add(e[0], e[4]), a02d = f2sub(e[0], e[4]);
    float2 a13s = f2add(e[2], e[6]), a13d = f2sub(e[2], e[6]);
    float2 A0 = f2add(a02s, a13s), A2 = f2sub(a02s, a13s);
    float2 A1, A3;
    if (FWD) {
        A1 = make_float2(a02d.x + a13d.y, a02d.y - a13d.x);
        A3 = make_float2(a02d.x - a13d.y, a02d.y + a13d.x);
    } else {
        A1 = make_float2(a02d.x - a13d.y, a02d.y + a13d.x);
        A3 = make_float2(a02d.x + a13d.y, a02d.y - a13d.x);
    }
    float2 b02s = f2add(e[1], e[5]), b02d = f2sub(e[1], e[5]);
    float2 b13s = f2add(e[3], e[7]), b13d = f2sub(e[3], e[7]);
    float2 B0 = f2add(b02s, b13s), B2 = f2sub(b02s, b13s);
    float2 B1, B3;
    if (FWD) {
        B1 = make_float2(b02d.x + b13d.y, b02d.y - b13d.x);
        B3 = make_float2(b02d.x - b13d.y, b02d.y + b13d.x);
    } else {
        B1 = make_float2(b02d.x - b13d.y, b02d.y + b13d.x);
        B3 = make_float2(b02d.x + b13d.y, b02d.y - b13d.x);
    }
    const float c = 0.7071067811865476f;
    float2 w1, w2, w3;
    if (FWD) {
        w1 = make_float2(c * (B1.x + B1.y), c * (B1.y - B1.x));
        w2 = make_float2(B2.y, -B2.x);
        w3 = make_float2(c * (B3.y - B3.x), -c * (B3.x + B3.y));
    } else {
        w1 = make_float2(c * (B1.x - B1.y), c * (B1.y + B1.x));
        w2 = make_float2(-B2.y, B2.x);
        w3 = make_float2(-c * (B3.x + B3.y), c * (B3.x - B3.y));
    }
    y[0] = f2add(A0, B0); y[4] = f2sub(A0, B0);
    y[1] = f2add(A1, w1); y[5] = f2sub(A1, w1);
    y[2] = f2add(A2, w2); y[6] = f2sub(A2, w2);
    y[3] = f2add(A3, w3); y[7] = f2sub(A3, w3);
}

template<int FWD>
__device__ float2* r8_stages(const float2* __restrict__ tw, float2* B0, float2* B1, int tid) {
    float2 *src = B0, *dst = B1;
    #pragma unroll 1
    for (int s3 = 3; s3 <= 9; s3 += 3) {
        const int m = 1 << s3;
        __syncthreads();
        const int jm = (tid >> s3) << s3;
        float2 e[8], y[8];
        #pragma unroll
        for (int q = 0; q < 8; q++) e[q] = src[skw3(tid + 512 * q)];
        dft8<FWD>(e, y);
        const int base = tid + 7 * jm;
        dst[skw3(base)] = y[0];
        #pragma unroll
        for (int p = 1; p < 8; p++) {
            float2 w = tw[p * jm];
            dst[skw3(base + p * m)] = FWD ? cmul(w, y[p]) : cmulc(w, y[p]);
        }
        float2* t = src; src = dst; dst = t;
    }
    __syncthreads();
    return src;
}

__device__ float2* inv_core(const float2* __restrict__ tw, float2* e,
                            float2* B0, float2* B1, int tid) {
    float2 y[8];
    dft8<0>(e, y);
    const int base = 8 * tid;
    B0[skw3(base)] = y[0];
    #pragma unroll
    for (int p = 1; p < 8; p++)
        B0[skw3(base + p)] = cmulc(tw[p * tid], y[p]);
    return r8_stages<0>(tw, B0, B1, tid);
}

// ---------------- kernel 0: init (feats=b, zero We/Wo + accumulators) ----------------
__global__ void init_kernel(const float* __restrict__ b) {
    int i = blockIdx.x * blockDim.x + threadIdx.x;
    if (i < 320 * FD) g_feats[i] = b[i & 511];
    if (i < 64 * FD) { g_We[i] = 0.0f; g_Wo[i] = 0.0f; }
    if (i == 0) { g_cons = 0.0f; g_contr = 0.0f; }
}

// ---------------- views helpers ----------------
__device__ __forceinline__ void store_hl8(size_t idx, const float* v) {
    __align__(16) __nv_bfloat16 hi[8], lo[8];
    #pragma unroll
    for (int q = 0; q < 8; q++) {
        __nv_bfloat16 h = __float2bfloat16_rn(v[q]);
        hi[q] = h;
        lo[q] = __float2bfloat16_rn(v[q] - __bfloat162float(h));
    }
    *(float4*)(g_Ah + idx) = *(float4*)hi;
    *(float4*)(g_Al + idx) = *(float4*)lo;
}
__device__ __forceinline__ void ldg8(float* v, const float* g) {
    float4 u0 = *(const float4*)g;
    float4 u1 = *(const float4*)(g + 4);
    v[0] = u0.x; v[1] = u0.y; v[2] = u0.z; v[3] = u0.w;
    v[4] = u1.x; v[5] = u1.y; v[6] = u1.z; v[7] = u1.w;
}

// ---------------- kernel 1: fused views + W split (+ We/Wo accumulation) ----------------
__global__ void __launch_bounds__(512, 2)
views_kernel(const float* __restrict__ x, const float* __restrict__ W,
             const float* __restrict__ nz1, const float* __restrict__ nz2,
             const int* __restrict__ pfs, const int* __restrict__ pts) {
    const int bx = blockIdx.x;
    const int grp = bx / 9, rr9 = bx % 9;
    const int tid = threadIdx.x;

    if (rr9 == 0) {
        // ---- W hi/lo split slice + We/Wo partial sums ----
        // slice = linear floats [grp*262144, (grp+1)*262144) = k-rows [grp*512, grp*512+512)
        // thread covers n columns n0..n0+8, k_local = j*8 + (tid>>6); parity(k) = (tid>>6)&1
        size_t base = (size_t)grp * 262144 + (size_t)tid * 8;
        float se[8] = {0,0,0,0,0,0,0,0};
        #pragma unroll 1
        for (int j = 0; j < 64; j++) {
            size_t i = base + (size_t)j * 4096;
            float vv[8];
            ldg8(vv, W + i);
            __align__(16) __nv_bfloat16 hi[8], lo[8];
            #pragma unroll
            for (int q = 0; q < 8; q++) {
                __nv_bfloat16 h = __float2bfloat16_rn(vv[q]);
                hi[q] = h;
                lo[q] = __float2bfloat16_rn(vv[q] - __bfloat162float(h));
                se[q] += vv[q];
            }
            *(float4*)(g_Wh + i) = *(float4*)hi;
            *(float4*)(g_Wl + i) = *(float4*)lo;
        }
        const int c = grp >> 3;
        const int n0 = (tid & 63) * 8;
        const float sgn = ((tid >> 6) & 1) ? -1.0f : 1.0f;
        #pragma unroll
        for (int q = 0; q < 8; q++) {
            atomicAdd(&g_We[c * FD + n0 + q], se[q]);
            atomicAdd(&g_Wo[c * FD + n0 + q], sgn * se[q]);
        }
        return;
    }

    extern __shared__ char smraw[];
    float2* tw = (float2*)smraw;
    float2* B0 = (float2*)(smraw + 32768);
    float2* B1 = B0 + PLANE3;
    __shared__ float red[32];

    const int row = grp * 8 + (rr9 - 1);
    const int bi = row >> 6, ci = row & 63;
    const int fs = *pfs, ts = *pts;
    const size_t xbase = (size_t)row * TT;

    // A rows: 0-63 x, 64-127 distorted, 128-191 noisy, 192-255 combined
    const size_t a0 = (size_t)(0*64 + bi) * KTOT + (size_t)ci * TT;
    const size_t a2 = (size_t)(1*64 + bi) * KTOT + (size_t)ci * TT;
    const size_t a3 = (size_t)(2*64 + bi) * KTOT + (size_t)ci * TT;
    const size_t a4 = (size_t)(3*64 + bi) * KTOT + (size_t)ci * TT;

    const int tc = 8 * tid;

    #pragma unroll
    for (int j = 0; j < 8; j++) {
        int k = tid + 512 * j;
        float s, c;
        sincospif(-(float)k * (1.0f / 2048.0f), &s, &c);
        tw[k] = make_float2(c, s);
    }

    float x8[8];
    ldg8(x8, x + xbase + tc);
    store_hl8(a0 + tc, x8);
    float ls = 0.0f, lq = 0.0f, la = 0.0f;
    #pragma unroll
    for (int j = 0; j < 8; j++) {
        ls += x8[j]; lq += x8[j] * x8[j];
        la += (j & 1) ? -x8[j] : x8[j];
    }
    {
        float* xs = (float*)B0;
        #pragma unroll
        for (int j = 0; j < 8; j++) xs[tc + j] = x8[j];
    }
    float X0 = blockReduceSum(ls, red);
    float q1 = blockReduceSum(lq, red);
    float X2048 = blockReduceSum(la, red);
    float std1 = sqrtf(fmaxf(0.0f, (q1 - X0 * X0 * (1.0f / 4096.0f)) * (1.0f / 4095.0f)));
    if (tid == 0) { g_X0[row] = X0; g_X2048[row] = X2048; }

    // noisy view
    {
        float n8[8], o8[8];
        ldg8(n8, nz1 + xbase + tc);
        #pragma unroll
        for (int j = 0; j < 8; j++) o8[j] = x8[j] + n8[j] * (0.02f * std1);
        store_hl8(a3 + tc, o8);
    }

    // pick up x in FFT register layout
    float xv[8];
    {
        const float* xs = (const float*)B0;
        #pragma unroll
        for (int j = 0; j < 8; j++) xv[j] = xs[tid + 512 * j];
    }
    __syncthreads();

    // forward stage 0
    {
        float2 e[8], y[8];
        #pragma unroll
        for (int q = 0; q < 8; q++) e[q] = make_float2(xv[q], 0.0f);
        dft8<1>(e, y);
        const int base = 8 * tid;
        B0[skw3(base)] = y[0];
        #pragma unroll
        for (int p = 1; p < 8; p++)
            B0[skw3(base + p)] = cmul(tw[p * tid], y[p]);
    }
    float2* Xp = r8_stages<1>(tw, B0, B1, tid);

    float2 Xr[8];
    #pragma unroll
    for (int j = 0; j < 8; j++) Xr[j] = Xp[skw3(tid + 512 * j)];

    // single packed inverse: distorted (Re) + combined-base (Im)
    {
        __syncthreads();
        float2 e[8];
        #pragma unroll
        for (int q = 0; q < 8; q++) {
            int k = tid + 512 * q;
            float ma = fmfold(k, fs);
            float mb = gmask(k) * ma;
            e[q] = make_float2(ma * Xr[q].x - mb * Xr[q].y,
                               ma * Xr[q].y + mb * Xr[q].x);
        }
        float2* r = inv_core(tw, e, B0, B1, tid);

        float od[8], vc[8];
        float ls2 = 0.0f, lq2 = 0.0f;
        #pragma unroll
        for (int j = 0; j < 8; j++) {
            int t = tc + j;
            float2 v = r[skw3(t)];
            float tm = (t >= ts && t < ts + 204) ? 0.1f : 1.0f;
            od[j] = tm * v.x * (1.0f / 4096.0f);
            float c = tm * v.y * (1.0f / 4096.0f);
            vc[j] = c;
            ls2 += c; lq2 += c * c;
        }
        store_hl8(a2 + tc, od);

        float s2 = blockReduceSum(ls2, red);
        float q2 = blockReduceSum(lq2, red);
        float std2 = sqrtf(fmaxf(0.0f, (q2 - s2 * s2 * (1.0f / 4096.0f)) * (1.0f / 4095.0f)));
        float n8[8], o8[8];
        ldg8(n8, nz2 + xbase + tc);
        #pragma unroll
        for (int j = 0; j < 8; j++) o8[j] = vc[j] + n8[j] * (0.02f * std2);
        store_hl8(a4 + tc, o8);
    }
}

// ---------------- kernel 2: GEMM (R11-proven pipeline, M=256) ----------------
#define STG 24576
#define GEMM_SMEM (3 * STG)

__global__ void __launch_bounds__(128, 3) gemm_kernel() {
    extern __shared__ char smbuf[];
    const uint32_t sb = smem_to_u32(smbuf);

    const int tid = threadIdx.x;
    const int warp = tid >> 5, lane = tid & 31;
    const int m0 = blockIdx.y * 64;
    const int n0 = blockIdx.x * 128;
    const int z = blockIdx.z;
    const int start_chunk = 372 * z + (z < 8 ? z : 8);
    const int nchunks = 372 + (z < 8 ? 1 : 0);

    const int wm = warp >> 1;
    const int wn = warp & 1;

    float acc[2][8][4];
    #pragma unroll
    for (int a = 0; a < 2; a++)
        #pragma unroll
        for (int b = 0; b < 8; b++)
            #pragma unroll
            for (int c = 0; c < 4; c++) acc[a][b][c] = 0.0f;

    const __nv_bfloat16* srcA[4];
    uint32_t dstA[4];
    #pragma unroll
    for (int i = 0; i < 2; i++) {
        int f = tid + 128 * i;
        int m = f >> 2, kc = f & 3;
        uint32_t rel = (uint32_t)(m * 64 + (((kc + (m >> 1)) & 3) << 4));
        size_t src = (size_t)(m0 + m) * KTOT + (size_t)start_chunk * 32 + kc * 8;
        dstA[i] = rel;            srcA[i] = g_Ah + src;
        dstA[i + 2] = rel + 4096; srcA[i + 2] = g_Al + src;
    }
    const __nv_bfloat16* srcW[8];
    uint32_t dstW[8];
    #pragma unroll
    for (int i = 0; i < 4; i++) {
        int f = tid + 128 * i;
        int k = f >> 4, nc = f & 15;
        uint32_t rel = (uint32_t)(8192 + k * 256 + (((nc ^ (k & 7)) & 15) << 4));
        size_t src = ((size_t)start_chunk * 32 + k) * 512 + n0 + nc * 8;
        dstW[i] = rel;            srcW[i] = g_Wh + src;
        dstW[i + 4] = rel + 8192; srcW[i + 4] = g_Wl + src;
    }

    uint32_t a_ld[2][2];
    {
        int tile = lane >> 3, r = lane & 7;
        #pragma unroll
        for (int mt = 0; mt < 2; mt++)
            #pragma unroll
            for (int kt = 0; kt < 2; kt++) {
                int mm = wm * 32 + mt * 16 + (tile & 1) * 8 + r;
                int kb = kt * 2 + (tile >> 1);
                a_ld[mt][kt] = (uint32_t)(mm * 64 + (((kb + (mm >> 1)) & 3) << 4));
            }
    }
    uint32_t b_ld4[4][2];
    {
        int lr = lane & 15, half = lane >> 4;
        #pragma unroll
        for (int ntp = 0; ntp < 4; ntp++) {
            int nb = wn * 8 + ntp * 2 + half;
            #pragma unroll
            for (int kt = 0; kt < 2; kt++) {
                int k = kt * 16 + lr;
                b_ld4[ntp][kt] = (uint32_t)(8192 + k * 256 + (((nb ^ (k & 7)) & 15) << 4));
            }
        }
    }

    auto issue = [&](uint32_t sbase) {
        #pragma unroll
        for (int i = 0; i < 4; i++) {
            cp_async16(sb + sbase + dstA[i], srcA[i]);
            srcA[i] += 32;
        }
        #pragma unroll
        for (int i = 0; i < 8; i++) {
            cp_async16(sb + sbase + dstW[i], srcW[i]);
            srcW[i] += 32 * 512;
        }
    };

    issue(0);       CP_COMMIT();
    issue(STG);     CP_COMMIT();

    int cur = 0, nxt2 = 2 * STG;
    for (int it = 0; it < nchunks; ++it) {
        if (it + 1 < nchunks) { CP_WAIT1(); } else { CP_WAIT0(); }
        __syncthreads();
        if (it + 2 < nchunks) {
            issue((uint32_t)nxt2);
            CP_COMMIT();
            nxt2 += STG; if (nxt2 == 3 * STG) nxt2 = 0;
        }
        const uint32_t cbase = (uint32_t)cur;
        cur += STG; if (cur == 3 * STG) cur = 0;

        #pragma unroll
        for (int kt = 0; kt < 2; kt++) {
            uint32_t ah[2][4], al[2][4];
            #pragma unroll
            for (int mt = 0; mt < 2; mt++) {
                ldsm_x4(ah[mt], sb + cbase + a_ld[mt][kt]);
                ldsm_x4(al[mt], sb + cbase + a_ld[mt][kt] + 4096);
            }
            uint32_t bh[16], bl[16];
            #pragma unroll
            for (int ntp = 0; ntp < 4; ntp++) {
                ldsm_x4_trans(&bh[ntp * 4], sb + cbase + b_ld4[ntp][kt]);
                ldsm_x4_trans(&bl[ntp * 4], sb + cbase + b_ld4[ntp][kt] + 8192);
            }
            #pragma unroll
            for (int mt = 0; mt < 2; mt++)
                #pragma unroll
                for (int nt = 0; nt < 8; nt++) {
                    mma_bf16(acc[mt][nt], ah[mt], &bh[nt * 2]);
                    mma_bf16(acc[mt][nt], ah[mt], &bl[nt * 2]);
                    mma_bf16(acc[mt][nt], al[mt], &bh[nt * 2]);
                }
        }
    }

    {
        const int g = lane >> 2, t4 = lane & 3;
        #pragma unroll
        for (int mt = 0; mt < 2; mt++) {
            int r0 = m0 + wm * 32 + mt * 16 + g;
            int r1 = r0 + 8;
            // A rows 0-63 -> feats rows 0-63 (orig); 64-255 -> feats 128-319
            int fr0 = (r0 < 64) ? r0 : r0 + 64;
            int fr1 = (r1 < 64) ? r1 : r1 + 64;
            #pragma unroll
            for (int nt = 0; nt < 8; nt++) {
                int col = n0 + wn * 64 + nt * 8 + t4 * 2;
                atomicAdd(&g_feats[fr0 * 512 + col],     acc[mt][nt][0]);
                atomicAdd(&g_feats[fr0 * 512 + col + 1], acc[mt][nt][1]);
                atomicAdd(&g_feats[fr1 * 512 + col],     acc[mt][nt][2]);
                atomicAdd(&g_feats[fr1 * 512 + col + 1], acc[mt][nt][3]);
            }
        }
    }
}

// ---------------- kernel 2b: compressed-view feats (closed form) ----------------
// feats[64+b][n] = 0.5*feats[b][n] + 0.5*bias[n] + (0.5/4096)*sum_c(X0[b,c]*We[c,n] - X2048[b,c]*Wo[c,n])
__global__ void __launch_bounds__(512) comp_kernel(const float* __restrict__ bias) {
    const int b = blockIdx.x;      // 0..63
    const int n = threadIdx.x;     // 0..511
    float acc = 0.0f;
    #pragma unroll 4
    for (int c = 0; c < 64; c++) {
        float x0 = g_X0[b * 64 + c];
        float x2 = g_X2048[b * 64 + c];
        acc += x0 * g_We[c * FD + n] - x2 * g_Wo[c * FD + n];
    }
    g_feats[(64 + b) * 512 + n] =
        0.5f * g_feats[b * 512 + n] + 0.5f * bias[n] + (0.5f / 4096.0f) * acc;
}

// ---------------- kernel 3: row norms + consistency ----------------
__global__ void post_kernel() {
    __shared__ float red[32];
    const int i = blockIdx.x;
    const int tid = threadIdx.x;
    const int base = i * 512;
    const int b0 = (i & 63) * 512;
    float sq = 0.0f, dsq = 0.0f;
    for (int f = tid; f < 512; f += 256) {
        float v = g_feats[base + f];
        sq += v * v;
        if (i >= 64) {
            float d = v - g_feats[b0 + f];
            dsq += d * d;
        }
    }
    float tsq = blockReduceSum(sq, red);
    float tdq = blockReduceSum(dsq, red);
    if (tid == 0) {
        g_norms[i] = sqrtf(tsq);
        if (i >= 64) atomicAdd(&g_cons, tdq);
    }
}

// ---------------- kernel 4: contrastive ----------------
__global__ void contr_kernel() {
    __shared__ float fi[512];
    __shared__ float simb[320];
    __shared__ float red[32];
    const int i = blockIdx.x;
    const int tid = threadIdx.x;
    for (int f = tid; f < 512; f += 256) fi[f] = g_feats[i * 512 + f];
    __syncthreads();
    const float inv_i = 1.0f / g_norms[i];
    const int w = tid >> 5, lane = tid & 31;
    for (int j = w; j < 320; j += 8) {
        float s = 0.0f;
        const float* fj = g_feats + j * 512;
        #pragma unroll 4
        for (int e = lane; e < 512; e += 32) s += fi[e] * fj[e];
        #pragma unroll
        for (int o = 16; o; o >>= 1) s += __shfl_down_sync(0xffffffffu, s, o);
        if (lane == 0) simb[j] = s * inv_i / g_norms[j] * 10.0f;
    }
    __syncthreads();
    float mx = -3.4e38f;
    for (int j = tid; j < 320; j += 256) mx = fmaxf(mx, simb[j]);
    mx = blockReduceMax(mx, red);
    float se = 0.0f;
    for (int j = tid; j < 320; j += 256) se += expf(simb[j] - mx);
    se = blockReduceSum(se, red);
    if (tid == 0) {
        float lse = mx + logf(se);
        float c = 0.0f;
        if (i > 0)   c += lse - simb[i - 1];
        if (i < 319) c += lse - simb[i + 1];
        atomicAdd(&g_contr, c);
    }
}

// ---------------- kernel 5: finalize ----------------
__global__ void fin_kernel(float* __restrict__ out) {
    out[0] = g_cons * (1.0f / 131072.0f) + 0.5f * (g_contr * (1.0f / 638.0f));
}

// ---------------- launch ----------------
#define VIEWS_SMEM (32768 + 2 * PLANE3 * 8)   /* 106496 */

extern "C" void kernel_launch(void* const* d_in, const int* in_sizes, int n_in,
                              void* d_out, int out_size) {
    const float* x  = (const float*)d_in[0];
    const float* W  = (const float*)d_in[1];
    const float* b  = (const float*)d_in[2];
    const float* n1 = (const float*)d_in[3];
    const float* n2 = (const float*)d_in[4];
    const int* fs   = (const int*)d_in[5];
    const int* ts   = (const int*)d_in[6];
    (void)in_sizes; (void)n_in; (void)out_size;

    cudaFuncSetAttribute(views_kernel, cudaFuncAttributeMaxDynamicSharedMemorySize, VIEWS_SMEM);
    cudaFuncSetAttribute(gemm_kernel, cudaFuncAttributeMaxDynamicSharedMemorySize, GEMM_SMEM);

    init_kernel<<<640, 256>>>(b);
    views_kernel<<<4608, 512, VIEWS_SMEM>>>(x, W, n1, n2, fs, ts);
    gemm_kernel<<<dim3(4, 4, 22), 128, GEMM_SMEM>>>();
    comp_kernel<<<64, 512>>>(b);
    post_kernel<<<320, 256>>>();
    contr_kernel<<<320, 256>>>();
    fin_kernel<<<1, 1>>>((float*)d_out);
}

// round 14
// speedup vs baseline: 1.1196x; 1.1196x over previous
#include <cuda_runtime.h>
#include <cuda_bf16.h>
#include <math.h>
#include <stdint.h>

#define TT 4096
#define KTOT (64*4096)   /* 262144 */
#define FD 512

// ---------------- scratch (static device globals) ----------------
__device__ __nv_bfloat16 g_Ah[(size_t)256 * KTOT];   // views: 0=x,1=distorted,2=noisy,3=combined
__device__ __nv_bfloat16 g_Al[(size_t)256 * KTOT];
__device__ __nv_bfloat16 g_Wh[(size_t)KTOT * FD];
__device__ __nv_bfloat16 g_Wl[(size_t)KTOT * FD];
__device__ float g_We[64 * FD];      // col-sums of W per c
__device__ float g_Wo[64 * FD];      // alternating col-sums
__device__ float g_X0[4096];         // per (b,c) row: sum of x
__device__ float g_X2048[4096];      // per (b,c) row: alternating sum
__device__ float g_feats[320 * FD];
__device__ float g_norms[320];
__device__ float g_cons;
__device__ float g_contr;

// ---------------- PTX helpers (baseline ISA only) ----------------
__device__ __forceinline__ uint32_t smem_to_u32(const void* p) {
    uint32_t a;
    asm("{ .reg .u64 t; cvta.to.shared.u64 t, %1; cvt.u32.u64 %0, t; }" : "=r"(a) : "l"(p));
    return a;
}
__device__ __forceinline__ void ldsm_x4(uint32_t* r, uint32_t addr) {
    asm volatile("ldmatrix.sync.aligned.m8n8.x4.shared.b16 {%0,%1,%2,%3}, [%4];"
        : "=r"(r[0]), "=r"(r[1]), "=r"(r[2]), "=r"(r[3]) : "r"(addr));
}
__device__ __forceinline__ void ldsm_x4_trans(uint32_t* r, uint32_t addr) {
    asm volatile("ldmatrix.sync.aligned.m8n8.x4.trans.shared.b16 {%0,%1,%2,%3}, [%4];"
        : "=r"(r[0]), "=r"(r[1]), "=r"(r[2]), "=r"(r[3]) : "r"(addr));
}
__device__ __forceinline__ void mma_bf16(float* c, const uint32_t* a, const uint32_t* b) {
    asm volatile("mma.sync.aligned.m16n8k16.row.col.f32.bf16.bf16.f32 "
        "{%0,%1,%2,%3}, {%4,%5,%6,%7}, {%8,%9}, {%0,%1,%2,%3};"
        : "+f"(c[0]), "+f"(c[1]), "+f"(c[2]), "+f"(c[3])
        : "r"(a[0]), "r"(a[1]), "r"(a[2]), "r"(a[3]), "r"(b[0]), "r"(b[1]));
}
__device__ __forceinline__ void cp_async16(uint32_t smem, const void* g) {
    asm volatile("cp.async.cg.shared.global [%0], [%1], 16;" :: "r"(smem), "l"(g));
}
#define CP_COMMIT() asm volatile("cp.async.commit_group;" ::: "memory")
#define CP_WAIT1()  asm volatile("cp.async.wait_group 1;" ::: "memory")
#define CP_WAIT0()  asm volatile("cp.async.wait_group 0;" ::: "memory")

// ---------------- block reductions ----------------
__device__ __forceinline__ float blockReduceSum(float v, float* red) {
    int lane = threadIdx.x & 31, w = threadIdx.x >> 5;
    int nw = blockDim.x >> 5;
    #pragma unroll
    for (int o = 16; o; o >>= 1) v += __shfl_down_sync(0xffffffffu, v, o);
    if (lane == 0) red[w] = v;
    __syncthreads();
    if (w == 0) {
        float r = (lane < nw) ? red[lane] : 0.0f;
        #pragma unroll
        for (int o = 8; o; o >>= 1) r += __shfl_down_sync(0xffffffffu, r, o);
        if (lane == 0) red[0] = r;
    }
    __syncthreads();
    float out = red[0];
    __syncthreads();
    return out;
}
__device__ __forceinline__ float blockReduceMax(float v, float* red) {
    int lane = threadIdx.x & 31, w = threadIdx.x >> 5;
    int nw = blockDim.x >> 5;
    #pragma unroll
    for (int o = 16; o; o >>= 1) v = fmaxf(v, __shfl_down_sync(0xffffffffu, v, o));
    if (lane == 0) red[w] = v;
    __syncthreads();
    if (w == 0) {
        float r = (lane < nw) ? red[lane] : -3.4e38f;
        #pragma unroll
        for (int o = 8; o; o >>= 1) r = fmaxf(r, __shfl_down_sync(0xffffffffu, r, o));
        if (lane == 0) red[0] = r;
    }
    __syncthreads();
    float out = red[0];
    __syncthreads();
    return out;
}

// ---------------- complex / masks / skew ----------------
__device__ __forceinline__ float2 f2add(float2 a, float2 b) { return make_float2(a.x + b.x, a.y + b.y); }
__device__ __forceinline__ float2 f2sub(float2 a, float2 b) { return make_float2(a.x - b.x, a.y - b.y); }
__device__ __forceinline__ float2 cmul(float2 a, float2 b) {
    return make_float2(a.x*b.x - a.y*b.y, a.x*b.y + a.y*b.x);
}
__device__ __forceinline__ float2 cmulc(float2 a, float2 b) {   // conj(a)*b
    return make_float2(a.x*b.x + a.y*b.y, a.x*b.y - a.y*b.x);
}
__device__ __forceinline__ float fmfold(int k, int fs) {
    float f1 = (k >= fs && k < fs + 409) ? 0.1f : 1.0f;
    int k2 = (4096 - k) & 4095;
    float f2 = (k2 >= fs && k2 < fs + 409) ? 0.1f : 1.0f;
    return 0.5f * (f1 + f2);
}
__device__ __forceinline__ float gmask(int k) {
    return (k == 0) ? 1.0f : ((k <= 1024) ? 0.5f : ((k < 3072) ? 1.0f : 0.5f));
}
__device__ __forceinline__ int skw3(int g) { return g + (g >> 3); }
#define PLANE3 4608

// ---------------- radix-8 butterfly ----------------
template<int FWD>
__device__ __forceinline__ void dft8(const float2* e, float2* y) {
    float2 a02s = f2add(e[0], e[4]), a02d = f2sub(e[0], e[4]);
    float2 a13s = f2add(e[2], e[6]), a13d = f2sub(e[2], e[6]);
    float2 A0 = f2add(a02s, a13s), A2 = f2sub(a02s, a13s);
    float2 A1, A3;
    if (FWD) {
        A1 = make_float2(a02d.x + a13d.y, a02d.y - a13d.x);
        A3 = make_float2(a02d.x - a13d.y, a02d.y + a13d.x);
    } else {
        A1 = make_float2(a02d.x - a13d.y, a02d.y + a13d.x);
        A3 = make_float2(a02d.x + a13d.y, a02d.y - a13d.x);
    }
    float2 b02s = f2add(e[1], e[5]), b02d = f2sub(e[1], e[5]);
    float2 b13s = f2add(e[3], e[7]), b13d = f2sub(e[3], e[7]);
    float2 B0 = f2add(b02s, b13s), B2 = f2sub(b02s, b13s);
    float2 B1, B3;
    if (FWD) {
        B1 = make_float2(b02d.x + b13d.y, b02d.y - b13d.x);
        B3 = make_float2(b02d.x - b13d.y, b02d.y + b13d.x);
    } else {
        B1 = make_float2(b02d.x - b13d.y, b02d.y + b13d.x);
        B3 = make_float2(b02d.x + b13d.y, b02d.y - b13d.x);
    }
    const float c = 0.7071067811865476f;
    float2 w1, w2, w3;
    if (FWD) {
        w1 = make_float2(c * (B1.x + B1.y), c * (B1.y - B1.x));
        w2 = make_float2(B2.y, -B2.x);
        w3 = make_float2(c * (B3.y - B3.x), -c * (B3.x + B3.y));
    } else {
        w1 = make_float2(c * (B1.x - B1.y), c * (B1.y + B1.x));
        w2 = make_float2(-B2.y, B2.x);
        w3 = make_float2(-c * (B3.x + B3.y), c * (B3.x - B3.y));
    }
    y[0] = f2add(A0, B0); y[4] = f2sub(A0, B0);
    y[1] = f2add(A1, w1); y[5] = f2sub(A1, w1);
    y[2] = f2add(A2, w2); y[6] = f2sub(A2, w2);
    y[3] = f2add(A3, w3); y[7] = f2sub(A3, w3);
}

template<int FWD>
__device__ float2* r8_stages(const float2* __restrict__ tw, float2* B0, float2* B1, int tid) {
    float2 *src = B0, *dst = B1;
    #pragma unroll 1
    for (int s3 = 3; s3 <= 9; s3 += 3) {
        const int m = 1 << s3;
        __syncthreads();
        const int jm = (tid >> s3) << s3;
        float2 e[8], y[8];
        #pragma unroll
        for (int q = 0; q < 8; q++) e[q] = src[skw3(tid + 512 * q)];
        dft8<FWD>(e, y);
        const int base = tid + 7 * jm;
        dst[skw3(base)] = y[0];
        #pragma unroll
        for (int p = 1; p < 8; p++) {
            float2 w = tw[p * jm];
            dst[skw3(base + p * m)] = FWD ? cmul(w, y[p]) : cmulc(w, y[p]);
        }
        float2* t = src; src = dst; dst = t;
    }
    __syncthreads();
    return src;
}

__device__ float2* inv_core(const float2* __restrict__ tw, float2* e,
                            float2* B0, float2* B1, int tid) {
    float2 y[8];
    dft8<0>(e, y);
    const int base = 8 * tid;
    B0[skw3(base)] = y[0];
    #pragma unroll
    for (int p = 1; p < 8; p++)
        B0[skw3(base + p)] = cmulc(tw[p * tid], y[p]);
    return r8_stages<0>(tw, B0, B1, tid);
}

// ---------------- kernel 0: init ----------------
__global__ void init_kernel(const float* __restrict__ b) {
    int i = blockIdx.x * blockDim.x + threadIdx.x;
    if (i < 320 * FD) g_feats[i] = b[i & 511];
    if (i < 64 * FD) { g_We[i] = 0.0f; g_Wo[i] = 0.0f; }
    if (i == 0) { g_cons = 0.0f; g_contr = 0.0f; }
}

// ---------------- views helpers ----------------
__device__ __forceinline__ void store_hl8(size_t idx, const float* v) {
    __align__(16) __nv_bfloat16 hi[8], lo[8];
    #pragma unroll
    for (int q = 0; q < 8; q++) {
        __nv_bfloat16 h = __float2bfloat16_rn(v[q]);
        hi[q] = h;
        lo[q] = __float2bfloat16_rn(v[q] - __bfloat162float(h));
    }
    *(float4*)(g_Ah + idx) = *(float4*)hi;
    *(float4*)(g_Al + idx) = *(float4*)lo;
}
__device__ __forceinline__ void ldg8(float* v, const float* g) {
    float4 u0 = *(const float4*)g;
    float4 u1 = *(const float4*)(g + 4);
    v[0] = u0.x; v[1] = u0.y; v[2] = u0.z; v[3] = u0.w;
    v[4] = u1.x; v[5] = u1.y; v[6] = u1.z; v[7] = u1.w;
}

// ---------------- kernel 1: fused views + W split (+ We/Wo accumulation) ----------------
__global__ void __launch_bounds__(512, 2)
views_kernel(const float* __restrict__ x, const float* __restrict__ W,
             const float* __restrict__ nz1, const float* __restrict__ nz2,
             const int* __restrict__ pfs, const int* __restrict__ pts) {
    const int bx = blockIdx.x;
    const int grp = bx / 9, rr9 = bx % 9;
    const int tid = threadIdx.x;

    if (rr9 == 0) {
        size_t base = (size_t)grp * 262144 + (size_t)tid * 8;
        float se[8] = {0,0,0,0,0,0,0,0};
        #pragma unroll 1
        for (int j = 0; j < 64; j++) {
            size_t i = base + (size_t)j * 4096;
            float vv[8];
            ldg8(vv, W + i);
            __align__(16) __nv_bfloat16 hi[8], lo[8];
            #pragma unroll
            for (int q = 0; q < 8; q++) {
                __nv_bfloat16 h = __float2bfloat16_rn(vv[q]);
                hi[q] = h;
                lo[q] = __float2bfloat16_rn(vv[q] - __bfloat162float(h));
                se[q] += vv[q];
            }
            *(float4*)(g_Wh + i) = *(float4*)hi;
            *(float4*)(g_Wl + i) = *(float4*)lo;
        }
        const int c = grp >> 3;
        const int n0 = (tid & 63) * 8;
        const float sgn = ((tid >> 6) & 1) ? -1.0f : 1.0f;
        #pragma unroll
        for (int q = 0; q < 8; q++) {
            atomicAdd(&g_We[c * FD + n0 + q], se[q]);
            atomicAdd(&g_Wo[c * FD + n0 + q], sgn * se[q]);
        }
        return;
    }

    extern __shared__ char smraw[];
    float2* tw = (float2*)smraw;
    float2* B0 = (float2*)(smraw + 32768);
    float2* B1 = B0 + PLANE3;
    __shared__ float red[32];

    const int row = grp * 8 + (rr9 - 1);
    const int bi = row >> 6, ci = row & 63;
    const int fs = *pfs, ts = *pts;
    const size_t xbase = (size_t)row * TT;

    const size_t a0 = (size_t)(0*64 + bi) * KTOT + (size_t)ci * TT;
    const size_t a2 = (size_t)(1*64 + bi) * KTOT + (size_t)ci * TT;
    const size_t a3 = (size_t)(2*64 + bi) * KTOT + (size_t)ci * TT;
    const size_t a4 = (size_t)(3*64 + bi) * KTOT + (size_t)ci * TT;

    const int tc = 8 * tid;

    #pragma unroll
    for (int j = 0; j < 8; j++) {
        int k = tid + 512 * j;
        float s, c;
        sincospif(-(float)k * (1.0f / 2048.0f), &s, &c);
        tw[k] = make_float2(c, s);
    }

    float x8[8];
    ldg8(x8, x + xbase + tc);
    store_hl8(a0 + tc, x8);
    float ls = 0.0f, lq = 0.0f, la = 0.0f;
    #pragma unroll
    for (int j = 0; j < 8; j++) {
        ls += x8[j]; lq += x8[j] * x8[j];
        la += (j & 1) ? -x8[j] : x8[j];
    }
    {
        float* xs = (float*)B0;
        #pragma unroll
        for (int j = 0; j < 8; j++) xs[tc + j] = x8[j];
    }
    float X0 = blockReduceSum(ls, red);
    float q1 = blockReduceSum(lq, red);
    float X2048 = blockReduceSum(la, red);
    float std1 = sqrtf(fmaxf(0.0f, (q1 - X0 * X0 * (1.0f / 4096.0f)) * (1.0f / 4095.0f)));
    if (tid == 0) { g_X0[row] = X0; g_X2048[row] = X2048; }

    {
        float n8[8], o8[8];
        ldg8(n8, nz1 + xbase + tc);
        #pragma unroll
        for (int j = 0; j < 8; j++) o8[j] = x8[j] + n8[j] * (0.02f * std1);
        store_hl8(a3 + tc, o8);
    }

    float xv[8];
    {
        const float* xs = (const float*)B0;
        #pragma unroll
        for (int j = 0; j < 8; j++) xv[j] = xs[tid + 512 * j];
    }
    __syncthreads();

    {
        float2 e[8], y[8];
        #pragma unroll
        for (int q = 0; q < 8; q++) e[q] = make_float2(xv[q], 0.0f);
        dft8<1>(e, y);
        const int base = 8 * tid;
        B0[skw3(base)] = y[0];
        #pragma unroll
        for (int p = 1; p < 8; p++)
            B0[skw3(base + p)] = cmul(tw[p * tid], y[p]);
    }
    float2* Xp = r8_stages<1>(tw, B0, B1, tid);

    float2 Xr[8];
    #pragma unroll
    for (int j = 0; j < 8; j++) Xr[j] = Xp[skw3(tid + 512 * j)];

    {
        __syncthreads();
        float2 e[8];
        #pragma unroll
        for (int q = 0; q < 8; q++) {
            int k = tid + 512 * q;
            float ma = fmfold(k, fs);
            float mb = gmask(k) * ma;
            e[q] = make_float2(ma * Xr[q].x - mb * Xr[q].y,
                               ma * Xr[q].y + mb * Xr[q].x);
        }
        float2* r = inv_core(tw, e, B0, B1, tid);

        float od[8], vc[8];
        float ls2 = 0.0f, lq2 = 0.0f;
        #pragma unroll
        for (int j = 0; j < 8; j++) {
            int t = tc + j;
            float2 v = r[skw3(t)];
            float tm = (t >= ts && t < ts + 204) ? 0.1f : 1.0f;
            od[j] = tm * v.x * (1.0f / 4096.0f);
            float c = tm * v.y * (1.0f / 4096.0f);
            vc[j] = c;
            ls2 += c; lq2 += c * c;
        }
        store_hl8(a2 + tc, od);

        float s2 = blockReduceSum(ls2, red);
        float q2 = blockReduceSum(lq2, red);
        float std2 = sqrtf(fmaxf(0.0f, (q2 - s2 * s2 * (1.0f / 4096.0f)) * (1.0f / 4095.0f)));
        float n8[8], o8[8];
        ldg8(n8, nz2 + xbase + tc);
        #pragma unroll
        for (int j = 0; j < 8; j++) o8[j] = vc[j] + n8[j] * (0.02f * std2);
        store_hl8(a4 + tc, o8);
    }
}

// ---------------- kernel 2: GEMM (R11 pipeline, M=256, ksplit=27) ----------------
#define STG 24576
#define GEMM_SMEM (3 * STG)
#define KSPL 27

__global__ void __launch_bounds__(128, 3) gemm_kernel() {
    extern __shared__ char smbuf[];
    const uint32_t sb = smem_to_u32(smbuf);

    const int tid = threadIdx.x;
    const int warp = tid >> 5, lane = tid & 31;
    const int m0 = blockIdx.y * 64;
    const int n0 = blockIdx.x * 128;
    const int z = blockIdx.z;
    // 8192 chunks over 27 slices: 303 each, first 11 get +1
    const int start_chunk = 303 * z + (z < 11 ? z : 11);
    const int nchunks = 303 + (z < 11 ? 1 : 0);

    const int wm = warp >> 1;
    const int wn = warp & 1;

    float acc[2][8][4];
    #pragma unroll
    for (int a = 0; a < 2; a++)
        #pragma unroll
        for (int b = 0; b < 8; b++)
            #pragma unroll
            for (int c = 0; c < 4; c++) acc[a][b][c] = 0.0f;

    const __nv_bfloat16* srcA[4];
    uint32_t dstA[4];
    #pragma unroll
    for (int i = 0; i < 2; i++) {
        int f = tid + 128 * i;
        int m = f >> 2, kc = f & 3;
        uint32_t rel = (uint32_t)(m * 64 + (((kc + (m >> 1)) & 3) << 4));
        size_t src = (size_t)(m0 + m) * KTOT + (size_t)start_chunk * 32 + kc * 8;
        dstA[i] = rel;            srcA[i] = g_Ah + src;
        dstA[i + 2] = rel + 4096; srcA[i + 2] = g_Al + src;
    }
    const __nv_bfloat16* srcW[8];
    uint32_t dstW[8];
    #pragma unroll
    for (int i = 0; i < 4; i++) {
        int f = tid + 128 * i;
        int k = f >> 4, nc = f & 15;
        uint32_t rel = (uint32_t)(8192 + k * 256 + (((nc ^ (k & 7)) & 15) << 4));
        size_t src = ((size_t)start_chunk * 32 + k) * 512 + n0 + nc * 8;
        dstW[i] = rel;            srcW[i] = g_Wh + src;
        dstW[i + 4] = rel + 8192; srcW[i + 4] = g_Wl + src;
    }

    uint32_t a_ld[2][2];
    {
        int tile = lane >> 3, r = lane & 7;
        #pragma unroll
        for (int mt = 0; mt < 2; mt++)
            #pragma unroll
            for (int kt = 0; kt < 2; kt++) {
                int mm = wm * 32 + mt * 16 + (tile & 1) * 8 + r;
                int kb = kt * 2 + (tile >> 1);
                a_ld[mt][kt] = (uint32_t)(mm * 64 + (((kb + (mm >> 1)) & 3) << 4));
            }
    }
    uint32_t b_ld4[4][2];
    {
        int lr = lane & 15, half = lane >> 4;
        #pragma unroll
        for (int ntp = 0; ntp < 4; ntp++) {
            int nb = wn * 8 + ntp * 2 + half;
            #pragma unroll
            for (int kt = 0; kt < 2; kt++) {
                int k = kt * 16 + lr;
                b_ld4[ntp][kt] = (uint32_t)(8192 + k * 256 + (((nb ^ (k & 7)) & 15) << 4));
            }
        }
    }

    auto issue = [&](uint32_t sbase) {
        #pragma unroll
        for (int i = 0; i < 4; i++) {
            cp_async16(sb + sbase + dstA[i], srcA[i]);
            srcA[i] += 32;
        }
        #pragma unroll
        for (int i = 0; i < 8; i++) {
            cp_async16(sb + sbase + dstW[i], srcW[i]);
            srcW[i] += 32 * 512;
        }
    };

    issue(0);       CP_COMMIT();
    issue(STG);     CP_COMMIT();

    int cur = 0, nxt2 = 2 * STG;
    for (int it = 0; it < nchunks; ++it) {
        if (it + 1 < nchunks) { CP_WAIT1(); } else { CP_WAIT0(); }
        __syncthreads();
        if (it + 2 < nchunks) {
            issue((uint32_t)nxt2);
            CP_COMMIT();
            nxt2 += STG; if (nxt2 == 3 * STG) nxt2 = 0;
        }
        const uint32_t cbase = (uint32_t)cur;
        cur += STG; if (cur == 3 * STG) cur = 0;

        #pragma unroll
        for (int kt = 0; kt < 2; kt++) {
            uint32_t ah[2][4], al[2][4];
            #pragma unroll
            for (int mt = 0; mt < 2; mt++) {
                ldsm_x4(ah[mt], sb + cbase + a_ld[mt][kt]);
                ldsm_x4(al[mt], sb + cbase + a_ld[mt][kt] + 4096);
            }
            uint32_t bh[16], bl[16];
            #pragma unroll
            for (int ntp = 0; ntp < 4; ntp++) {
                ldsm_x4_trans(&bh[ntp * 4], sb + cbase + b_ld4[ntp][kt]);
                ldsm_x4_trans(&bl[ntp * 4], sb + cbase + b_ld4[ntp][kt] + 8192);
            }
            #pragma unroll
            for (int mt = 0; mt < 2; mt++)
                #pragma unroll
                for (int nt = 0; nt < 8; nt++) {
                    mma_bf16(acc[mt][nt], ah[mt], &bh[nt * 2]);
                    mma_bf16(acc[mt][nt], ah[mt], &bl[nt * 2]);
                    mma_bf16(acc[mt][nt], al[mt], &bh[nt * 2]);
                }
        }
    }

    {
        const int g = lane >> 2, t4 = lane & 3;
        #pragma unroll
        for (int mt = 0; mt < 2; mt++) {
            int r0 = m0 + wm * 32 + mt * 16 + g;
            int r1 = r0 + 8;
            int fr0 = (r0 < 64) ? r0 : r0 + 64;
            int fr1 = (r1 < 64) ? r1 : r1 + 64;
            #pragma unroll
            for (int nt = 0; nt < 8; nt++) {
                int col = n0 + wn * 64 + nt * 8 + t4 * 2;
                atomicAdd(&g_feats[fr0 * 512 + col],     acc[mt][nt][0]);
                atomicAdd(&g_feats[fr0 * 512 + col + 1], acc[mt][nt][1]);
                atomicAdd(&g_feats[fr1 * 512 + col],     acc[mt][nt][2]);
                atomicAdd(&g_feats[fr1 * 512 + col + 1], acc[mt][nt][3]);
            }
        }
    }
}

// ---------------- kernel 2b: compressed-view feats (closed form) ----------------
__global__ void __launch_bounds__(512) comp_kernel(const float* __restrict__ bias) {
    const int b = blockIdx.x;      // 0..63
    const int n = threadIdx.x;     // 0..511
    float acc = 0.0f;
    #pragma unroll 4
    for (int c = 0; c < 64; c++) {
        float x0 = g_X0[b * 64 + c];
        float x2 = g_X2048[b * 64 + c];
        acc += x0 * g_We[c * FD + n] - x2 * g_Wo[c * FD + n];
    }
    g_feats[(64 + b) * 512 + n] =
        0.5f * g_feats[b * 512 + n] + 0.5f * bias[n] + (0.5f / 4096.0f) * acc;
}

// ---------------- kernel 3: row norms + consistency ----------------
__global__ void post_kernel() {
    __shared__ float red[32];
    const int i = blockIdx.x;
    const int tid = threadIdx.x;
    const int base = i * 512;
    const int b0 = (i & 63) * 512;
    float sq = 0.0f, dsq = 0.0f;
    for (int f = tid; f < 512; f += 256) {
        float v = g_feats[base + f];
        sq += v * v;
        if (i >= 64) {
            float d = v - g_feats[b0 + f];
            dsq += d * d;
        }
    }
    float tsq = blockReduceSum(sq, red);
    float tdq = blockReduceSum(dsq, red);
    if (tid == 0) {
        g_norms[i] = sqrtf(tsq);
        if (i >= 64) atomicAdd(&g_cons, tdq);
    }
}

// ---------------- kernel 4: contrastive ----------------
__global__ void contr_kernel() {
    __shared__ float fi[512];
    __shared__ float simb[320];
    __shared__ float red[32];
    const int i = blockIdx.x;
    const int tid = threadIdx.x;
    for (int f = tid; f < 512; f += 256) fi[f] = g_feats[i * 512 + f];
    __syncthreads();
    const float inv_i = 1.0f / g_norms[i];
    const int w = tid >> 5, lane = tid & 31;
    for (int j = w; j < 320; j += 8) {
        float s = 0.0f;
        const float* fj = g_feats + j * 512;
        #pragma unroll 4
        for (int e = lane; e < 512; e += 32) s += fi[e] * fj[e];
        #pragma unroll
        for (int o = 16; o; o >>= 1) s += __shfl_down_sync(0xffffffffu, s, o);
        if (lane == 0) simb[j] = s * inv_i / g_norms[j] * 10.0f;
    }
    __syncthreads();
    float mx = -3.4e38f;
    for (int j = tid; j < 320; j += 256) mx = fmaxf(mx, simb[j]);
    mx = blockReduceMax(mx, red);
    float se = 0.0f;
    for (int j = tid; j < 320; j += 256) se += expf(simb[j] - mx);
    se = blockReduceSum(se, red);
    if (tid == 0) {
        float lse = mx + logf(se);
        float c = 0.0f;
        if (i > 0)   c += lse - simb[i - 1];
        if (i < 319) c += lse - simb[i + 1];
        atomicAdd(&g_contr, c);
    }
}

// ---------------- kernel 5: finalize ----------------
__global__ void fin_kernel(float* __restrict__ out) {
    out[0] = g_cons * (1.0f / 131072.0f) + 0.5f * (g_contr * (1.0f / 638.0f));
}

// ---------------- launch ----------------
#define VIEWS_SMEM (32768 + 2 * PLANE3 * 8)   /* 106496 */

extern "C" void kernel_launch(void* const* d_in, const int* in_sizes, int n_in,
                              void* d_out, int out_size) {
    const float* x  = (const float*)d_in[0];
    const float* W  = (const float*)d_in[1];
    const float* b  = (const float*)d_in[2];
    const float* n1 = (const float*)d_in[3];
    const float* n2 = (const float*)d_in[4];
    const int* fs   = (const int*)d_in[5];
    const int* ts   = (const int*)d_in[6];
    (void)in_sizes; (void)n_in; (void)out_size;

    cudaFuncSetAttribute(views_kernel, cudaFuncAttributeMaxDynamicSharedMemorySize, VIEWS_SMEM);
    cudaFuncSetAttribute(gemm_kernel, cudaFuncAttributeMaxDynamicSharedMemorySize, GEMM_SMEM);

    init_kernel<<<640, 256>>>(b);
    views_kernel<<<4608, 512, VIEWS_SMEM>>>(x, W, n1, n2, fs, ts);
    gemm_kernel<<<dim3(4, 4, KSPL), 128, GEMM_SMEM>>>();
    comp_kernel<<<64, 512>>>(b);
    post_kernel<<<320, 256>>>();
    contr_kernel<<<320, 256>>>();
    fin_kernel<<<1, 1>>>((float*)d_out);
}

// round 15
// speedup vs baseline: 1.1391x; 1.0174x over previous
#include <cuda_runtime.h>
#include <cuda_bf16.h>
#include <math.h>
#include <stdint.h>

#define TT 4096
#define KTOT (64*4096)   /* 262144 */
#define FD 512

// ---------------- scratch (static device globals) ----------------
__device__ float g_A[(size_t)256 * KTOT];    // tf32-rounded fp32; rows: 0-63 x, 64-127 dist, 128-191 noisy, 192-255 comb
__device__ float g_Wt[(size_t)FD * KTOT];    // W^T [n][k], tf32-rounded fp32
__device__ float g_We[64 * FD];
__device__ float g_Wo[64 * FD];
__device__ float g_X0[4096];
__device__ float g_X2048[4096];
__device__ float g_feats[320 * FD];
__device__ float g_norms[320];
__device__ float g_cons;
__device__ float g_contr;

// ---------------- PTX helpers (baseline ISA only) ----------------
__device__ __forceinline__ uint32_t smem_to_u32(const void* p) {
    uint32_t a;
    asm("{ .reg .u64 t; cvta.to.shared.u64 t, %1; cvt.u32.u64 %0, t; }" : "=r"(a) : "l"(p));
    return a;
}
__device__ __forceinline__ void ldsm_x4(uint32_t* r, uint32_t addr) {
    asm volatile("ldmatrix.sync.aligned.m8n8.x4.shared.b16 {%0,%1,%2,%3}, [%4];"
        : "=r"(r[0]), "=r"(r[1]), "=r"(r[2]), "=r"(r[3]) : "r"(addr));
}
__device__ __forceinline__ void mma_tf32(float* c, const uint32_t* a, const uint32_t* b) {
    asm volatile("mma.sync.aligned.m16n8k8.row.col.f32.tf32.tf32.f32 "
        "{%0,%1,%2,%3}, {%4,%5,%6,%7}, {%8,%9}, {%0,%1,%2,%3};"
        : "+f"(c[0]), "+f"(c[1]), "+f"(c[2]), "+f"(c[3])
        : "r"(a[0]), "r"(a[1]), "r"(a[2]), "r"(a[3]), "r"(b[0]), "r"(b[1]));
}
__device__ __forceinline__ void cp_async16(uint32_t smem, const void* g) {
    asm volatile("cp.async.cg.shared.global [%0], [%1], 16;" :: "r"(smem), "l"(g));
}
#define CP_COMMIT() asm volatile("cp.async.commit_group;" ::: "memory")
#define CP_WAIT1()  asm volatile("cp.async.wait_group 1;" ::: "memory")
#define CP_WAIT0()  asm volatile("cp.async.wait_group 0;" ::: "memory")

__device__ __forceinline__ float rna_tf32(float v) {
    uint32_t r;
    asm("cvt.rna.tf32.f32 %0, %1;" : "=r"(r) : "f"(v));
    return __uint_as_float(r);
}

// ---------------- block reductions ----------------
__device__ __forceinline__ float blockReduceSum(float v, float* red) {
    int lane = threadIdx.x & 31, w = threadIdx.x >> 5;
    int nw = blockDim.x >> 5;
    #pragma unroll
    for (int o = 16; o; o >>= 1) v += __shfl_down_sync(0xffffffffu, v, o);
    if (lane == 0) red[w] = v;
    __syncthreads();
    if (w == 0) {
        float r = (lane < nw) ? red[lane] : 0.0f;
        #pragma unroll
        for (int o = 8; o; o >>= 1) r += __shfl_down_sync(0xffffffffu, r, o);
        if (lane == 0) red[0] = r;
    }
    __syncthreads();
    float out = red[0];
    __syncthreads();
    return out;
}
__device__ __forceinline__ float blockReduceMax(float v, float* red) {
    int lane = threadIdx.x & 31, w = threadIdx.x >> 5;
    int nw = blockDim.x >> 5;
    #pragma unroll
    for (int o = 16; o; o >>= 1) v = fmaxf(v, __shfl_down_sync(0xffffffffu, v, o));
    if (lane == 0) red[w] = v;
    __syncthreads();
    if (w == 0) {
        float r = (lane < nw) ? red[lane] : -3.4e38f;
        #pragma unroll
        for (int o = 8; o; o >>= 1) r = fmaxf(r, __shfl_down_sync(0xffffffffu, r, o));
        if (lane == 0) red[0] = r;
    }
    __syncthreads();
    float out = red[0];
    __syncthreads();
    return out;
}

// ---------------- complex / masks / skew ----------------
__device__ __forceinline__ float2 f2add(float2 a, float2 b) { return make_float2(a.x + b.x, a.y + b.y); }
__device__ __forceinline__ float2 f2sub(float2 a, float2 b) { return make_float2(a.x - b.x, a.y - b.y); }
__device__ __forceinline__ float2 cmul(float2 a, float2 b) {
    return make_float2(a.x*b.x - a.y*b.y, a.x*b.y + a.y*b.x);
}
__device__ __forceinline__ float2 cmulc(float2 a, float2 b) {
    return make_float2(a.x*b.x + a.y*b.y, a.x*b.y - a.y*b.x);
}
__device__ __forceinline__ float fmfold(int k, int fs) {
    float f1 = (k >= fs && k < fs + 409) ? 0.1f : 1.0f;
    int k2 = (4096 - k) & 4095;
    float f2 = (k2 >= fs && k2 < fs + 409) ? 0.1f : 1.0f;
    return 0.5f * (f1 + f2);
}
__device__ __forceinline__ float gmask(int k) {
    return (k == 0) ? 1.0f : ((k <= 1024) ? 0.5f : ((k < 3072) ? 1.0f : 0.5f));
}
__device__ __forceinline__ int skw3(int g) { return g + (g >> 3); }
#define PLANE3 4608

// ---------------- radix-8 butterfly ----------------
template<int FWD>
__device__ __forceinline__ void dft8(const float2* e, float2* y) {
    float2 a02s = f2add(e[0], e[4]), a02d = f2sub(e[0], e[4]);
    float2 a13s = f2add(e[2], e[6]), a13d = f2sub(e[2], e[6]);
    float2 A0 = f2add(a02s, a13s), A2 = f2sub(a02s, a13s);
    float2 A1, A3;
    if (FWD) {
        A1 = make_float2(a02d.x + a13d.y, a02d.y - a13d.x);
        A3 = make_float2(a02d.x - a13d.y, a02d.y + a13d.x);
    } else {
        A1 = make_float2(a02d.x - a13d.y, a02d.y + a13d.x);
        A3 = make_float2(a02d.x + a13d.y, a02d.y - a13d.x);
    }
    float2 b02s = f2add(e[1], e[5]), b02d = f2sub(e[1], e[5]);
    float2 b13s = f2add(e[3], e[7]), b13d = f2sub(e[3], e[7]);
    float2 B0 = f2add(b02s, b13s), B2 = f2sub(b02s, b13s);
    float2 B1, B3;
    if (FWD) {
        B1 = make_float2(b02d.x + b13d.y, b02d.y - b13d.x);
        B3 = make_float2(b02d.x - b13d.y, b02d.y + b13d.x);
    } else {
        B1 = make_float2(b02d.x - b13d.y, b02d.y + b13d.x);
        B3 = make_float2(b02d.x + b13d.y, b02d.y - b13d.x);
    }
    const float c = 0.7071067811865476f;
    float2 w1, w2, w3;
    if (FWD) {
        w1 = make_float2(c * (B1.x + B1.y), c * (B1.y - B1.x));
        w2 = make_float2(B2.y, -B2.x);
        w3 = make_float2(c * (B3.y - B3.x), -c * (B3.x + B3.y));
    } else {
        w1 = make_float2(c * (B1.x - B1.y), c * (B1.y + B1.x));
        w2 = make_float2(-B2.y, B2.x);
        w3 = make_float2(-c * (B3.x + B3.y), c * (B3.x - B3.y));
    }
    y[0] = f2add(A0, B0); y[4] = f2sub(A0, B0);
    y[1] = f2add(A1, w1); y[5] = f2sub(A1, w1);
    y[2] = f2add(A2, w2); y[6] = f2sub(A2, w2);
    y[3] = f2add(A3, w3); y[7] = f2sub(A3, w3);
}

template<int FWD>
__device__ float2* r8_stages(const float2* __restrict__ tw, float2* B0, float2* B1, int tid) {
    float2 *src = B0, *dst = B1;
    #pragma unroll 1
    for (int s3 = 3; s3 <= 9; s3 += 3) {
        const int m = 1 << s3;
        __syncthreads();
        const int jm = (tid >> s3) << s3;
        float2 e[8], y[8];
        #pragma unroll
        for (int q = 0; q < 8; q++) e[q] = src[skw3(tid + 512 * q)];
        dft8<FWD>(e, y);
        const int base = tid + 7 * jm;
        dst[skw3(base)] = y[0];
        #pragma unroll
        for (int p = 1; p < 8; p++) {
            float2 w = tw[p * jm];
            dst[skw3(base + p * m)] = FWD ? cmul(w, y[p]) : cmulc(w, y[p]);
        }
        float2* t = src; src = dst; dst = t;
    }
    __syncthreads();
    return src;
}

__device__ float2* inv_core(const float2* __restrict__ tw, float2* e,
                            float2* B0, float2* B1, int tid) {
    float2 y[8];
    dft8<0>(e, y);
    const int base = 8 * tid;
    B0[skw3(base)] = y[0];
    #pragma unroll
    for (int p = 1; p < 8; p++)
        B0[skw3(base + p)] = cmulc(tw[p * tid], y[p]);
    return r8_stages<0>(tw, B0, B1, tid);
}

// ---------------- kernel 0: init ----------------
__global__ void init_kernel(const float* __restrict__ b) {
    int i = blockIdx.x * blockDim.x + threadIdx.x;
    if (i < 320 * FD) g_feats[i] = b[i & 511];
    if (i < 64 * FD) { g_We[i] = 0.0f; g_Wo[i] = 0.0f; }
    if (i == 0) { g_cons = 0.0f; g_contr = 0.0f; }
}

// ---------------- views helpers ----------------
__device__ __forceinline__ void store8f(size_t idx, const float* v) {
    __align__(16) float o[8];
    #pragma unroll
    for (int q = 0; q < 8; q++) o[q] = rna_tf32(v[q]);
    *(float4*)(g_A + idx)     = *(float4*)&o[0];
    *(float4*)(g_A + idx + 4) = *(float4*)&o[4];
}
__device__ __forceinline__ void ldg8(float* v, const float* g) {
    float4 u0 = *(const float4*)g;
    float4 u1 = *(const float4*)(g + 4);
    v[0] = u0.x; v[1] = u0.y; v[2] = u0.z; v[3] = u0.w;
    v[4] = u1.x; v[5] = u1.y; v[6] = u1.z; v[7] = u1.w;
}

// ---------------- kernel 1: fused views + W transpose (+ We/Wo) ----------------
__global__ void __launch_bounds__(512, 2)
views_kernel(const float* __restrict__ x, const float* __restrict__ W,
             const float* __restrict__ nz1, const float* __restrict__ nz2,
             const int* __restrict__ pfs, const int* __restrict__ pts) {
    const int bx = blockIdx.x;
    const int grp = bx / 9, rr9 = bx % 9;
    const int tid = threadIdx.x;

    extern __shared__ char smraw[];

    if (rr9 == 0) {
        // ---- W transpose slice: k-rows [grp*512, grp*512+512), all 512 n ----
        float* tile = (float*)smraw;     // 64*65 floats
        const int c = grp >> 3;
        const int nn = (tid >> 3);       // 0..63 (local n within nt8 tile)
        const int kk = tid >> 3;         // load-phase row
        const int nf = (tid & 7) * 8;    // load-phase col offset
        const int kk8 = (tid & 7) * 8;   // store-phase k offset
        #pragma unroll 1
        for (int nt8 = 0; nt8 < 8; nt8++) {
            float se = 0.0f, so = 0.0f;
            const int ng = nt8 * 64 + nn;
            #pragma unroll 1
            for (int kt8 = 0; kt8 < 8; kt8++) {
                {
                    const float* src = W + (size_t)(grp * 512 + kt8 * 64 + kk) * 512 + nt8 * 64 + nf;
                    float v[8];
                    ldg8(v, src);
                    float* d = &tile[kk * 65 + nf];
                    #pragma unroll
                    for (int q = 0; q < 8; q++) d[q] = v[q];
                }
                __syncthreads();
                {
                    __align__(16) float o[8];
                    #pragma unroll
                    for (int j = 0; j < 8; j++) {
                        float w = tile[(kk8 + j) * 65 + nn];
                        se += w;
                        so += (j & 1) ? -w : w;
                        o[j] = rna_tf32(w);
                    }
                    size_t dst = (size_t)ng * KTOT + (size_t)(grp * 512 + kt8 * 64 + kk8);
                    *(float4*)(g_Wt + dst)     = *(float4*)&o[0];
                    *(float4*)(g_Wt + dst + 4) = *(float4*)&o[4];
                }
                __syncthreads();
            }
            atomicAdd(&g_We[c * FD + ng], se);
            atomicAdd(&g_Wo[c * FD + ng], so);
        }
        return;
    }

    float2* tw = (float2*)smraw;
    float2* B0 = (float2*)(smraw + 32768);
    float2* B1 = B0 + PLANE3;
    __shared__ float red[32];

    const int row = grp * 8 + (rr9 - 1);
    const int bi = row >> 6, ci = row & 63;
    const int fs = *pfs, ts = *pts;
    const size_t xbase = (size_t)row * TT;

    const size_t a0 = (size_t)(0*64 + bi) * KTOT + (size_t)ci * TT;
    const size_t a2 = (size_t)(1*64 + bi) * KTOT + (size_t)ci * TT;
    const size_t a3 = (size_t)(2*64 + bi) * KTOT + (size_t)ci * TT;
    const size_t a4 = (size_t)(3*64 + bi) * KTOT + (size_t)ci * TT;

    const int tc = 8 * tid;

    #pragma unroll
    for (int j = 0; j < 8; j++) {
        int k = tid + 512 * j;
        float s, c;
        sincospif(-(float)k * (1.0f / 2048.0f), &s, &c);
        tw[k] = make_float2(c, s);
    }

    float x8[8];
    ldg8(x8, x + xbase + tc);
    store8f(a0 + tc, x8);
    float ls = 0.0f, lq = 0.0f, la = 0.0f;
    #pragma unroll
    for (int j = 0; j < 8; j++) {
        ls += x8[j]; lq += x8[j] * x8[j];
        la += (j & 1) ? -x8[j] : x8[j];
    }
    {
        float* xs = (float*)B0;
        #pragma unroll
        for (int j = 0; j < 8; j++) xs[tc + j] = x8[j];
    }
    float X0 = blockReduceSum(ls, red);
    float q1 = blockReduceSum(lq, red);
    float X2048 = blockReduceSum(la, red);
    float std1 = sqrtf(fmaxf(0.0f, (q1 - X0 * X0 * (1.0f / 4096.0f)) * (1.0f / 4095.0f)));
    if (tid == 0) { g_X0[row] = X0; g_X2048[row] = X2048; }

    {
        float n8[8], o8[8];
        ldg8(n8, nz1 + xbase + tc);
        #pragma unroll
        for (int j = 0; j < 8; j++) o8[j] = x8[j] + n8[j] * (0.02f * std1);
        store8f(a3 + tc, o8);
    }

    float xv[8];
    {
        const float* xs = (const float*)B0;
        #pragma unroll
        for (int j = 0; j < 8; j++) xv[j] = xs[tid + 512 * j];
    }
    __syncthreads();

    {
        float2 e[8], y[8];
        #pragma unroll
        for (int q = 0; q < 8; q++) e[q] = make_float2(xv[q], 0.0f);
        dft8<1>(e, y);
        const int base = 8 * tid;
        B0[skw3(base)] = y[0];
        #pragma unroll
        for (int p = 1; p < 8; p++)
            B0[skw3(base + p)] = cmul(tw[p * tid], y[p]);
    }
    float2* Xp = r8_stages<1>(tw, B0, B1, tid);

    float2 Xr[8];
    #pragma unroll
    for (int j = 0; j < 8; j++) Xr[j] = Xp[skw3(tid + 512 * j)];

    {
        __syncthreads();
        float2 e[8];
        #pragma unroll
        for (int q = 0; q < 8; q++) {
            int k = tid + 512 * q;
            float ma = fmfold(k, fs);
            float mb = gmask(k) * ma;
            e[q] = make_float2(ma * Xr[q].x - mb * Xr[q].y,
                               ma * Xr[q].y + mb * Xr[q].x);
        }
        float2* r = inv_core(tw, e, B0, B1, tid);

        float od[8], vc[8];
        float ls2 = 0.0f, lq2 = 0.0f;
        #pragma unroll
        for (int j = 0; j < 8; j++) {
            int t = tc + j;
            float2 v = r[skw3(t)];
            float tm = (t >= ts && t < ts + 204) ? 0.1f : 1.0f;
            od[j] = tm * v.x * (1.0f / 4096.0f);
            float c = tm * v.y * (1.0f / 4096.0f);
            vc[j] = c;
            ls2 += c; lq2 += c * c;
        }
        store8f(a2 + tc, od);

        float s2 = blockReduceSum(ls2, red);
        float q2 = blockReduceSum(lq2, red);
        float std2 = sqrtf(fmaxf(0.0f, (q2 - s2 * s2 * (1.0f / 4096.0f)) * (1.0f / 4095.0f)));
        float n8[8], o8[8];
        ldg8(n8, nz2 + xbase + tc);
        #pragma unroll
        for (int j = 0; j < 8; j++) o8[j] = vc[j] + n8[j] * (0.02f * std2);
        store8f(a4 + tc, o8);
    }
}

// ---------------- kernel 2: tf32 GEMM (single-term, M=256, ksplit=27) ----------------
// stage (24576 B): A [64][32] fp32 at 0 (8KB), Wt [128][32] fp32 at 8192 (16KB)
// smem row = 128B = 8 chunks; chunk swizzle: phys = kc ^ (row & 7)
#define STG 24576
#define GEMM_SMEM (3 * STG)
#define KSPL 27

__global__ void __launch_bounds__(128, 3) gemm_kernel() {
    extern __shared__ char smbuf[];
    const uint32_t sb = smem_to_u32(smbuf);

    const int tid = threadIdx.x;
    const int warp = tid >> 5, lane = tid & 31;
    const int m0 = blockIdx.y * 64;
    const int n0 = blockIdx.x * 128;
    const int z = blockIdx.z;
    const int start_chunk = 303 * z + (z < 11 ? z : 11);   // 8192 k32-chunks over 27
    const int nchunks = 303 + (z < 11 ? 1 : 0);

    const int wm = warp >> 1;
    const int wn = warp & 1;

    float acc[2][8][4];
    #pragma unroll
    for (int a = 0; a < 2; a++)
        #pragma unroll
        for (int b = 0; b < 8; b++)
            #pragma unroll
            for (int c = 0; c < 4; c++) acc[a][b][c] = 0.0f;

    // cp.async: A 512 chunks (4/thread), Wt 1024 chunks (8/thread)
    const int rA = tid >> 3;          // 0..15 base row
    const int kcA = tid & 7;
    const float* srcA0 = g_A + (size_t)(m0 + rA) * KTOT + (size_t)start_chunk * 32 + kcA * 4;
    const uint32_t dstA0 = (uint32_t)(rA * 128 + ((kcA ^ (rA & 7)) << 4));
    const float* srcW0 = g_Wt + (size_t)(n0 + rA) * KTOT + (size_t)start_chunk * 32 + kcA * 4;
    const uint32_t dstW0 = (uint32_t)(8192 + rA * 128 + ((kcA ^ (rA & 7)) << 4));

    // ldmatrix base addresses (ks=0 / p=0), XOR-offset for other steps
    uint32_t a_addr[2];
    {
        int rrow0 = wm * 32 + (lane & 7) + 8 * ((lane >> 3) & 1);
        int h = lane >> 4;
        #pragma unroll
        for (int mt = 0; mt < 2; mt++) {
            int rrow = rrow0 + mt * 16;
            a_addr[mt] = (uint32_t)(rrow * 128 + (((h ^ (rrow & 7)) & 7) << 4));
        }
    }
    uint32_t b_addr[8];
    {
        int ch0 = lane >> 3;          // 0..3
        #pragma unroll
        for (int nt = 0; nt < 8; nt++) {
            int rrow = wn * 64 + nt * 8 + (lane & 7);
            b_addr[nt] = (uint32_t)(8192 + rrow * 128 + (((ch0 ^ (rrow & 7)) & 7) << 4));
        }
    }

    long srcOff = 0;   // float offset advance
    auto issue = [&](uint32_t sbase) {
        #pragma unroll
        for (int i = 0; i < 4; i++)
            cp_async16(sb + sbase + dstA0 + 2048 * i, srcA0 + srcOff + (size_t)i * 16 * KTOT);
        #pragma unroll
        for (int i = 0; i < 8; i++)
            cp_async16(sb + sbase + dstW0 + 2048 * i, srcW0 + srcOff + (size_t)i * 16 * KTOT);
        srcOff += 32;
    };

    issue(0);       CP_COMMIT();
    issue(STG);     CP_COMMIT();

    int cur = 0, nxt2 = 2 * STG;
    for (int it = 0; it < nchunks; ++it) {
        if (it + 1 < nchunks) { CP_WAIT1(); } else { CP_WAIT0(); }
        __syncthreads();
        if (it + 2 < nchunks) {
            issue((uint32_t)nxt2);
            CP_COMMIT();
            nxt2 += STG; if (nxt2 == 3 * STG) nxt2 = 0;
        }
        const uint32_t cbase = (uint32_t)cur;
        cur += STG; if (cur == 3 * STG) cur = 0;

        #pragma unroll
        for (int p = 0; p < 2; p++) {
            uint32_t bf[8][4];
            #pragma unroll
            for (int nt = 0; nt < 8; nt++)
                ldsm_x4(bf[nt], sb + cbase + (b_addr[nt] ^ ((uint32_t)p << 6)));
            #pragma unroll
            for (int ksl = 0; ksl < 2; ksl++) {
                const uint32_t kxor = (uint32_t)(2 * p + ksl) << 5;
                uint32_t af[2][4];
                #pragma unroll
                for (int mt = 0; mt < 2; mt++)
                    ldsm_x4(af[mt], sb + cbase + (a_addr[mt] ^ kxor));
                #pragma unroll
                for (int mt = 0; mt < 2; mt++)
                    #pragma unroll
                    for (int nt = 0; nt < 8; nt++)
                        mma_tf32(acc[mt][nt], af[mt], &bf[nt][2 * ksl]);
            }
        }
    }

    {
        const int g = lane >> 2, t4 = lane & 3;
        #pragma unroll
        for (int mt = 0; mt < 2; mt++) {
            int r0 = m0 + wm * 32 + mt * 16 + g;
            int r1 = r0 + 8;
            int fr0 = (r0 < 64) ? r0 : r0 + 64;
            int fr1 = (r1 < 64) ? r1 : r1 + 64;
            #pragma unroll
            for (int nt = 0; nt < 8; nt++) {
                int col = n0 + wn * 64 + nt * 8 + t4 * 2;
                atomicAdd(&g_feats[fr0 * 512 + col],     acc[mt][nt][0]);
                atomicAdd(&g_feats[fr0 * 512 + col + 1], acc[mt][nt][1]);
                atomicAdd(&g_feats[fr1 * 512 + col],     acc[mt][nt][2]);
                atomicAdd(&g_feats[fr1 * 512 + col + 1], acc[mt][nt][3]);
            }
        }
    }
}

// ---------------- kernel 2b: compressed-view feats (closed form) ----------------
__global__ void __launch_bounds__(512) comp_kernel(const float* __restrict__ bias) {
    const int b = blockIdx.x;
    const int n = threadIdx.x;
    float acc = 0.0f;
    #pragma unroll 4
    for (int c = 0; c < 64; c++) {
        float x0 = g_X0[b * 64 + c];
        float x2 = g_X2048[b * 64 + c];
        acc += x0 * g_We[c * FD + n] - x2 * g_Wo[c * FD + n];
    }
    g_feats[(64 + b) * 512 + n] =
        0.5f * g_feats[b * 512 + n] + 0.5f * bias[n] + (0.5f / 4096.0f) * acc;
}

// ---------------- kernel 3: row norms + consistency ----------------
__global__ void post_kernel() {
    __shared__ float red[32];
    const int i = blockIdx.x;
    const int tid = threadIdx.x;
    const int base = i * 512;
    const int b0 = (i & 63) * 512;
    float sq = 0.0f, dsq = 0.0f;
    for (int f = tid; f < 512; f += 256) {
        float v = g_feats[base + f];
        sq += v * v;
        if (i >= 64) {
            float d = v - g_feats[b0 + f];
            dsq += d * d;
        }
    }
    float tsq = blockReduceSum(sq, red);
    float tdq = blockReduceSum(dsq, red);
    if (tid == 0) {
        g_norms[i] = sqrtf(tsq);
        if (i >= 64) atomicAdd(&g_cons, tdq);
    }
}

// ---------------- kernel 4: contrastive ----------------
__global__ void contr_kernel() {
    __shared__ float fi[512];
    __shared__ float simb[320];
    __shared__ float red[32];
    const int i = blockIdx.x;
    const int tid = threadIdx.x;
    for (int f = tid; f < 512; f += 256) fi[f] = g_feats[i * 512 + f];
    __syncthreads();
    const float inv_i = 1.0f / g_norms[i];
    const int w = tid >> 5, lane = tid & 31;
    for (int j = w; j < 320; j += 8) {
        float s = 0.0f;
        const float* fj = g_feats + j * 512;
        #pragma unroll 4
        for (int e = lane; e < 512; e += 32) s += fi[e] * fj[e];
        #pragma unroll
        for (int o = 16; o; o >>= 1) s += __shfl_down_sync(0xffffffffu, s, o);
        if (lane == 0) simb[j] = s * inv_i / g_norms[j] * 10.0f;
    }
    __syncthreads();
    float mx = -3.4e38f;
    for (int j = tid; j < 320; j += 256) mx = fmaxf(mx, simb[j]);
    mx = blockReduceMax(mx, red);
    float se = 0.0f;
    for (int j = tid; j < 320; j += 256) se += expf(simb[j] - mx);
    se = blockReduceSum(se, red);
    if (tid == 0) {
        float lse = mx + logf(se);
        float c = 0.0f;
        if (i > 0)   c += lse - simb[i - 1];
        if (i < 319) c += lse - simb[i + 1];
        atomicAdd(&g_contr, c);
    }
}

// ---------------- kernel 5: finalize ----------------
__global__ void fin_kernel(float* __restrict__ out) {
    out[0] = g_cons * (1.0f / 131072.0f) + 0.5f * (g_contr * (1.0f / 638.0f));
}

// ---------------- launch ----------------
#define VIEWS_SMEM (32768 + 2 * PLANE3 * 8)   /* 106496 */

extern "C" void kernel_launch(void* const* d_in, const int* in_sizes, int n_in,
                              void* d_out, int out_size) {
    const float* x  = (const float*)d_in[0];
    const float* W  = (const float*)d_in[1];
    const float* b  = (const float*)d_in[2];
    const float* n1 = (const float*)d_in[3];
    const float* n2 = (const float*)d_in[4];
    const int* fs   = (const int*)d_in[5];
    const int* ts   = (const int*)d_in[6];
    (void)in_sizes; (void)n_in; (void)out_size;

    cudaFuncSetAttribute(views_kernel, cudaFuncAttributeMaxDynamicSharedMemorySize, VIEWS_SMEM);
    cudaFuncSetAttribute(gemm_kernel, cudaFuncAttributeMaxDynamicSharedMemorySize, GEMM_SMEM);

    init_kernel<<<640, 256>>>(b);
    views_kernel<<<4608, 512, VIEWS_SMEM>>>(x, W, n1, n2, fs, ts);
    gemm_kernel<<<dim3(4, 4, KSPL), 128, GEMM_SMEM>>>();
    comp_kernel<<<64, 512>>>(b);
    post_kernel<<<320, 256>>>();
    contr_kernel<<<320, 256>>>();
    fin_kernel<<<1, 1>>>((float*)d_out);
}